// round 1
// baseline (speedup 1.0000x reference)
#include <cuda_runtime.h>

typedef unsigned long long ull;

#define LOG2E_F  1.4426950408889634f
#define LOG2PI_F 1.8378770664093453f
#define KCOMP 8
#define TPB 256
#define ELEMS_PER_THREAD 8   // two float4 loads
#define ELEMS_PER_BLOCK (TPB * ELEMS_PER_THREAD)  // 2048

// ---- packed f32x2 helpers (sm_100+ dual-issue fp32) ----
__device__ __forceinline__ ull pk2(float a, float b) {
    ull r; asm("mov.b64 %0, {%1, %2};" : "=l"(r) : "f"(a), "f"(b)); return r;
}
__device__ __forceinline__ void upk2(ull v, float& a, float& b) {
    asm("mov.b64 {%0, %1}, %2;" : "=f"(a), "=f"(b) : "l"(v));
}
__device__ __forceinline__ ull add2(ull a, ull b) {
    ull r; asm("add.rn.f32x2 %0, %1, %2;" : "=l"(r) : "l"(a), "l"(b)); return r;
}
__device__ __forceinline__ ull mul2(ull a, ull b) {
    ull r; asm("mul.rn.f32x2 %0, %1, %2;" : "=l"(r) : "l"(a), "l"(b)); return r;
}
__device__ __forceinline__ ull fma2(ull a, ull b, ull c) {
    ull r; asm("fma.rn.f32x2 %0, %1, %2, %3;" : "=l"(r) : "l"(a), "l"(b), "l"(c)); return r;
}
__device__ __forceinline__ float ex2f_fast(float x) {
    float r; asm("ex2.approx.ftz.f32 %0, %1;" : "=f"(r) : "f"(x)); return r;
}
__device__ __forceinline__ float rcpf_fast(float x) {
    float r; asm("rcp.approx.ftz.f32 %0, %1;" : "=f"(r) : "f"(x)); return r;
}

__global__ __launch_bounds__(TPB) void gmm_hscore_kernel(
    const float4* __restrict__ x4,
    const float*  __restrict__ mean,
    const float*  __restrict__ logvar,
    const float*  __restrict__ logweight,
    float4*       __restrict__ out4)
{
    // ---- per-block constant precompute (K=8, negligible cost) ----
    __shared__ float s_nmu[KCOMP];   // -mu_k
    __shared__ float s_c2n[KCOMP];   // -0.5 * invvar * log2(e)   (EX2 arg scale)
    __shared__ float s_ck[KCOMP];    // exp(logweight - 0.5*(lv + LOG2PI))
    __shared__ float s_ninv[KCOMP];  // -invvar

    const int t = threadIdx.x;
    if (t < KCOMP) {
        float lv = logvar[t];
        float iv = ex2f_fast(-lv * LOG2E_F);          // exp(-lv) = 1/var
        s_nmu[t]  = -mean[t];
        s_ninv[t] = -iv;
        s_c2n[t]  = -0.5f * iv * LOG2E_F;
        s_ck[t]   = ex2f_fast((logweight[t] - 0.5f * (lv + LOG2PI_F)) * LOG2E_F);
    }
    __syncthreads();

    // Broadcast constants into packed registers (duplicated lanes)
    ull nmu2[KCOMP], c2n2[KCOMP], ck2[KCOMP], ninv2[KCOMP];
    #pragma unroll
    for (int k = 0; k < KCOMP; k++) {
        float a = s_nmu[k], b = s_c2n[k], c = s_ck[k], d = s_ninv[k];
        nmu2[k]  = pk2(a, a);
        c2n2[k]  = pk2(b, b);
        ck2[k]   = pk2(c, c);
        ninv2[k] = pk2(d, d);
    }

    // ---- load 8 elements (two coalesced float4) ----
    const int base = blockIdx.x * (2 * TPB) + t;   // in float4 units
    float4 xa = x4[base];
    float4 xb = x4[base + TPB];

    ull X[4];
    X[0] = pk2(xa.x, xa.y);
    X[1] = pk2(xa.z, xa.w);
    X[2] = pk2(xb.x, xb.y);
    X[3] = pk2(xb.z, xb.w);

    ull MP[4], MD[4], DD[4];
    const ull Z = pk2(0.0f, 0.0f);
    #pragma unroll
    for (int p = 0; p < 4; p++) { MP[p] = Z; MD[p] = Z; DD[p] = Z; }

    // ---- main loop: 4 pairs x 8 components ----
    #pragma unroll
    for (int p = 0; p < 4; p++) {
        #pragma unroll
        for (int k = 0; k < KCOMP; k++) {
            ull D = add2(X[p], nmu2[k]);        // diff = x - mu
            ull Q = mul2(D, c2n2[k]);
            ull T = mul2(Q, D);                 // -0.5*diff^2*invvar*log2e
            float t0, t1; upk2(T, t0, t1);
            float e0 = ex2f_fast(t0);
            float e1 = ex2f_fast(t1);
            ull E = pk2(e0, e1);
            ull P = mul2(E, ck2[k]);            // prob contribution
            MP[p] = add2(MP[p], P);             // mpdf
            ull S = mul2(D, ninv2[k]);          // s = -diff*invvar
            MD[p] = fma2(P, S, MD[p]);          // mdpdf
            ull U = fma2(S, S, ninv2[k]);       // s^2 - invvar
            DD[p] = fma2(P, U, DD[p]);          // ddpdf
        }
    }

    // ---- epilogue: hscore = -0.5*(md/mp)^2 + dd/mp ----
    float h[8];
    #pragma unroll
    for (int p = 0; p < 4; p++) {
        float mp0, mp1, md0, md1, dd0, dd1;
        upk2(MP[p], mp0, mp1);
        upk2(MD[p], md0, md1);
        upk2(DD[p], dd0, dd1);
        float r0 = rcpf_fast(mp0);
        float r1 = rcpf_fast(mp1);
        float dl0 = md0 * r0;
        float dl1 = md1 * r1;
        h[2*p+0] = fmaf(-0.5f * dl0, dl0, dd0 * r0);
        h[2*p+1] = fmaf(-0.5f * dl1, dl1, dd1 * r1);
    }

    float4 oa = make_float4(h[0], h[1], h[2], h[3]);
    float4 ob = make_float4(h[4], h[5], h[6], h[7]);
    out4[base]       = oa;
    out4[base + TPB] = ob;
}

extern "C" void kernel_launch(void* const* d_in, const int* in_sizes, int n_in,
                              void* d_out, int out_size) {
    const float4* x4        = (const float4*)d_in[0];
    const float*  mean      = (const float*)d_in[1];
    const float*  logvar    = (const float*)d_in[2];
    const float*  logweight = (const float*)d_in[3];
    float4*       out4      = (float4*)d_out;

    int n = in_sizes[0];                      // 4194304, divisible by 2048
    int blocks = n / ELEMS_PER_BLOCK;
    gmm_hscore_kernel<<<blocks, TPB>>>(x4, mean, logvar, logweight, out4);
}